// round 1
// baseline (speedup 1.0000x reference)
#include <cuda_runtime.h>

typedef unsigned long long ull;

#define BN_TOTAL 16384   // B*N
#define NN 2048

// Scratch (static device arrays — no allocation)
__device__ float g_wpk[576];                         // packed conv weights [3][48][4]
__device__ __align__(16) float g_eip[BN_TOTAL];
__device__ __align__(16) float g_ein[BN_TOTAL];
__device__ __align__(16) float g_ejp[BN_TOTAL];
__device__ __align__(16) float g_ejn[BN_TOTAL];

// ---------------------------------------------------------------------------
// k0: rearrange conv weights (co,ci,1,3) -> [c][k*16+ci][co] for packed FMA
// ---------------------------------------------------------------------------
__global__ void prep_kernel(const float* __restrict__ cw1,
                            const float* __restrict__ cw2,
                            const float* __restrict__ cw3) {
    int tid = threadIdx.x;
    if (tid < 576) {
        int c   = tid / 192;
        int r   = tid % 192;
        int pos = r >> 2;      // k*16 + ci
        int co  = r & 3;
        int k   = pos >> 4;
        int ci  = pos & 15;
        const float* cw = (c == 0) ? cw1 : ((c == 1) ? cw2 : cw3);
        g_wpk[tid] = cw[co * 48 + ci * 3 + k];
    }
}

__device__ __forceinline__ void fma2(ull& acc, ull x, ull w) {
    asm("fma.rn.f32x2 %0, %1, %2, %0;" : "+l"(acc) : "l"(x), "l"(w));
}
__device__ __forceinline__ ull pack2(float v) {
    ull r; unsigned u = __float_as_uint(v);
    asm("mov.b64 %0, {%1, %1};" : "=l"(r) : "r"(u));
    return r;
}

// ---------------------------------------------------------------------------
// k1: fused TimeBlock conv + dot with wi/wj -> exp factors per (b,n)
// One warp per (b,n); lane = output time index 'to' (two rounds for 62).
// ---------------------------------------------------------------------------
__global__ void __launch_bounds__(256) score_kernel(
    const float* __restrict__ X,
    const float* __restrict__ cb1, const float* __restrict__ cb2,
    const float* __restrict__ cb3,
    const float* __restrict__ fcw, const float* __restrict__ fcbp)
{
    __shared__ __align__(16) float sX[8 * 1088];   // 8 warps x 64 rows x 17 (pad)
    __shared__ __align__(16) float sW[576];
    __shared__ float sFC[496];

    int tid = threadIdx.x;
    for (int i = tid; i < 576; i += 256) sW[i]  = g_wpk[i];
    for (int i = tid; i < 496; i += 256) sFC[i] = fcw[i];

    int warp = tid >> 5, lane = tid & 31;
    int bn = blockIdx.x * 8 + warp;

    // cooperative load of X[bn] (64x16 floats) into padded shared tile
    const float4* Xg = (const float4*)(X + (size_t)bn * 1024);
    #pragma unroll
    for (int q = 0; q < 8; q++) {
        int f = lane + q * 32;
        float4 v = Xg[f];
        int row = f >> 2, c4 = (f & 3) * 4;
        float* d = sX + warp * 1088 + row * 17 + c4;
        d[0] = v.x; d[1] = v.y; d[2] = v.z; d[3] = v.w;
    }
    __syncthreads();

    float b1_[4], b2_[4], b3_[4];
    #pragma unroll
    for (int co = 0; co < 4; co++) { b1_[co] = cb1[co]; b2_[co] = cb2[co]; b3_[co] = cb3[co]; }

    float si = 0.f, sj = 0.f;
    #pragma unroll 1
    for (int r = 0; r < 2; r++) {
        int to = r * 32 + lane;
        if (to < 62) {
            ull a0 = 0, a1 = 0, a2 = 0, a3 = 0, a4 = 0, a5 = 0;
            const float* xb = sX + warp * 1088 + to * 17;
            #pragma unroll
            for (int k = 0; k < 3; k++) {
                #pragma unroll
                for (int ci = 0; ci < 16; ci++) {
                    ull xx = pack2(xb[k * 17 + ci]);
                    int wb = (k * 16 + ci) * 4;
                    fma2(a0, xx, *(const ull*)(sW + wb));
                    fma2(a1, xx, *(const ull*)(sW + wb + 2));
                    fma2(a2, xx, *(const ull*)(sW + 192 + wb));
                    fma2(a3, xx, *(const ull*)(sW + 192 + wb + 2));
                    fma2(a4, xx, *(const ull*)(sW + 384 + wb));
                    fma2(a5, xx, *(const ull*)(sW + 384 + wb + 2));
                }
            }
            float y1[4], y2[4], y3[4];
            y1[0] = __uint_as_float((unsigned)a0); y1[1] = __uint_as_float((unsigned)(a0 >> 32));
            y1[2] = __uint_as_float((unsigned)a1); y1[3] = __uint_as_float((unsigned)(a1 >> 32));
            y2[0] = __uint_as_float((unsigned)a2); y2[1] = __uint_as_float((unsigned)(a2 >> 32));
            y2[2] = __uint_as_float((unsigned)a3); y2[3] = __uint_as_float((unsigned)(a3 >> 32));
            y3[0] = __uint_as_float((unsigned)a4); y3[1] = __uint_as_float((unsigned)(a4 >> 32));
            y3[2] = __uint_as_float((unsigned)a5); y3[3] = __uint_as_float((unsigned)(a5 >> 32));
            #pragma unroll
            for (int co = 0; co < 4; co++) {
                float v2 = y2[co] + b2_[co];
                float sg = 1.0f / (1.0f + __expf(-v2));
                float tv = (y1[co] + b1_[co]) + sg + (y3[co] + b3_[co]);
                tv = fmaxf(tv, 0.0f);
                si = fmaf(tv, sFC[to * 4 + co], si);
                sj = fmaf(tv, sFC[248 + to * 4 + co], sj);
            }
        }
    }
    #pragma unroll
    for (int off = 16; off > 0; off >>= 1) {
        si += __shfl_xor_sync(0xffffffffu, si, off);
        sj += __shfl_xor_sync(0xffffffffu, sj, off);
    }
    if (lane == 0) {
        float fcb = fcbp[0];
        float sif = si + fcb;
        g_eip[bn] = __expf(sif);
        g_ein[bn] = __expf(0.01f * sif);
        g_ejp[bn] = __expf(sj);
        g_ejn[bn] = __expf(0.01f * sj);
    }
}

// ---------------------------------------------------------------------------
// k2: masked softmax row kernel. One block per (b,i) output row.
// exp(leaky(si+sj+c)) = max(Eip*Ejp[j], Ein*Ejn[j])  (no MUFU in hot loop)
// masked entries contribute exp(0)=1 to the denominator.
// ---------------------------------------------------------------------------
__global__ void __launch_bounds__(256) softmax_kernel(
    const float* __restrict__ A, float* __restrict__ out)
{
    int bid = blockIdx.x;
    int b = bid >> 11;
    int i = bid & 2047;
    int t = threadIdx.x;

    const float4* A4 = (const float4*)(A + (size_t)i * NN);
    const float4* P4 = (const float4*)(g_ejp + b * NN);
    const float4* Q4 = (const float4*)(g_ejn + b * NN);
    float Eip = g_eip[bid];
    float Ein = g_ein[bid];

    float4 a0 = A4[t],       a1 = A4[t + 256];
    float4 p0 = P4[t],       p1 = P4[t + 256];
    float4 q0 = Q4[t],       q1 = Q4[t + 256];

    float4 e0, e1;
    e0.x = fmaxf(Eip * p0.x, Ein * q0.x);
    e0.y = fmaxf(Eip * p0.y, Ein * q0.y);
    e0.z = fmaxf(Eip * p0.z, Ein * q0.z);
    e0.w = fmaxf(Eip * p0.w, Ein * q0.w);
    e1.x = fmaxf(Eip * p1.x, Ein * q1.x);
    e1.y = fmaxf(Eip * p1.y, Ein * q1.y);
    e1.z = fmaxf(Eip * p1.z, Ein * q1.z);
    e1.w = fmaxf(Eip * p1.w, Ein * q1.w);

    float acc = ((a0.x != 0.f) ? e0.x : 1.f) + ((a0.y != 0.f) ? e0.y : 1.f)
              + ((a0.z != 0.f) ? e0.z : 1.f) + ((a0.w != 0.f) ? e0.w : 1.f)
              + ((a1.x != 0.f) ? e1.x : 1.f) + ((a1.y != 0.f) ? e1.y : 1.f)
              + ((a1.z != 0.f) ? e1.z : 1.f) + ((a1.w != 0.f) ? e1.w : 1.f);

    #pragma unroll
    for (int off = 16; off > 0; off >>= 1)
        acc += __shfl_xor_sync(0xffffffffu, acc, off);

    __shared__ float red[8];
    __shared__ float s_r;
    if ((t & 31) == 0) red[t >> 5] = acc;
    __syncthreads();
    if (t == 0) {
        float s = red[0] + red[1] + red[2] + red[3]
                + red[4] + red[5] + red[6] + red[7];
        s_r = 1.0f / s;
    }
    __syncthreads();
    float r = s_r;

    float4* O = (float4*)(out + (size_t)bid * NN);
    float4 o0, o1;
    o0.x = e0.x * a0.x * r;  o0.y = e0.y * a0.y * r;
    o0.z = e0.z * a0.z * r;  o0.w = e0.w * a0.w * r;
    o1.x = e1.x * a1.x * r;  o1.y = e1.y * a1.y * r;
    o1.z = e1.z * a1.z * r;  o1.w = e1.w * a1.w * r;
    O[t]       = o0;
    O[t + 256] = o1;
}

// ---------------------------------------------------------------------------
extern "C" void kernel_launch(void* const* d_in, const int* in_sizes, int n_in,
                              void* d_out, int out_size) {
    const float* X   = (const float*)d_in[0];
    const float* A   = (const float*)d_in[1];
    const float* cw1 = (const float*)d_in[2];
    const float* cb1 = (const float*)d_in[3];
    const float* cw2 = (const float*)d_in[4];
    const float* cb2 = (const float*)d_in[5];
    const float* cw3 = (const float*)d_in[6];
    const float* cb3 = (const float*)d_in[7];
    const float* fcw = (const float*)d_in[8];
    const float* fcb = (const float*)d_in[9];
    float* out = (float*)d_out;

    prep_kernel<<<1, 576>>>(cw1, cw2, cw3);
    score_kernel<<<BN_TOTAL / 8, 256>>>(X, cb1, cb2, cb3, fcw, fcb);
    softmax_kernel<<<BN_TOTAL, 256>>>(A, out);
}

// round 2
// speedup vs baseline: 5.7164x; 5.7164x over previous
#include <cuda_runtime.h>

typedef unsigned long long ull;

#define BN_TOTAL 16384   // B*N
#define NN 2048

__device__ __align__(16) float g_eip[BN_TOTAL];
__device__ __align__(16) float g_ein[BN_TOTAL];
__device__ __align__(16) float g_ejp[BN_TOTAL];
__device__ __align__(16) float g_ejn[BN_TOTAL];

__device__ __forceinline__ void fma2(ull& acc, ull x, ull w) {
    asm("fma.rn.f32x2 %0, %1, %2, %0;" : "+l"(acc) : "l"(x), "l"(w));
}
__device__ __forceinline__ ull pack2(float v) {
    ull r; unsigned u = __float_as_uint(v);
    asm("mov.b64 %0, {%1, %1};" : "=l"(r) : "r"(u));
    return r;
}

// ---------------------------------------------------------------------------
// k1: fused TimeBlock conv + dot with wi/wj -> exp factors per (b,n).
// One warp per (b,n). Lane handles to=lane and to2=lane+32 (if <62), so
// every weight load from shared is reused for two output positions.
// ---------------------------------------------------------------------------
__global__ void __launch_bounds__(256) score_kernel(
    const float* __restrict__ X,
    const float* __restrict__ cw1, const float* __restrict__ cw2,
    const float* __restrict__ cw3,
    const float* __restrict__ cb1, const float* __restrict__ cb2,
    const float* __restrict__ cb3,
    const float* __restrict__ fcw, const float* __restrict__ fcbp)
{
    __shared__ __align__(16) float sX[8 * 1088];   // 8 warps x 64 rows x 17 (pad)
    __shared__ __align__(16) float sW[576];        // [c][k*16+ci][co]
    __shared__ float sFC[496];

    int tid = threadIdx.x;
    // pack conv weights: (co,ci,1,3) -> [c][(k*16+ci)][co]
    for (int i = tid; i < 576; i += 256) {
        int c   = i / 192;
        int r   = i % 192;
        int pos = r >> 2, co = r & 3;
        int k   = pos >> 4, ci = pos & 15;
        const float* cw = (c == 0) ? cw1 : ((c == 1) ? cw2 : cw3);
        sW[i] = cw[co * 48 + ci * 3 + k];
    }
    for (int i = tid; i < 496; i += 256) sFC[i] = fcw[i];

    int warp = tid >> 5, lane = tid & 31;
    int bn = blockIdx.x * 8 + warp;

    // cooperative load of X[bn] (64x16 floats) into padded shared tile
    const float4* Xg = (const float4*)(X + (size_t)bn * 1024);
    #pragma unroll
    for (int q = 0; q < 8; q++) {
        int f = lane + q * 32;
        float4 v = Xg[f];
        int row = f >> 2, c4 = (f & 3) * 4;
        float* d = sX + warp * 1088 + row * 17 + c4;
        d[0] = v.x; d[1] = v.y; d[2] = v.z; d[3] = v.w;
    }
    __syncthreads();

    int to  = lane;        // 0..31  (always < 62)
    int to2 = lane + 32;   // 32..63 (valid if < 62)

    ull A0 = 0, A1 = 0, A2 = 0, A3 = 0, A4 = 0, A5 = 0;
    ull B0 = 0, B1 = 0, B2 = 0, B3 = 0, B4 = 0, B5 = 0;
    const float* x1 = sX + warp * 1088 + to * 17;
    const float* x2 = x1 + 32 * 17;     // rows 32..63 all in-bounds

    #pragma unroll
    for (int k = 0; k < 3; k++) {
        #pragma unroll
        for (int ci = 0; ci < 16; ci++) {
            int wb = (k * 16 + ci) * 4;
            ull w0 = *(const ull*)(sW + wb);
            ull w1 = *(const ull*)(sW + wb + 2);
            ull w2 = *(const ull*)(sW + 192 + wb);
            ull w3 = *(const ull*)(sW + 192 + wb + 2);
            ull w4 = *(const ull*)(sW + 384 + wb);
            ull w5 = *(const ull*)(sW + 384 + wb + 2);
            ull xa = pack2(x1[k * 17 + ci]);
            ull xb = pack2(x2[k * 17 + ci]);
            fma2(A0, xa, w0); fma2(A1, xa, w1);
            fma2(A2, xa, w2); fma2(A3, xa, w3);
            fma2(A4, xa, w4); fma2(A5, xa, w5);
            fma2(B0, xb, w0); fma2(B1, xb, w1);
            fma2(B2, xb, w2); fma2(B3, xb, w3);
            fma2(B4, xb, w4); fma2(B5, xb, w5);
        }
    }

    float b1_[4], b2_[4], b3_[4];
    #pragma unroll
    for (int co = 0; co < 4; co++) { b1_[co] = cb1[co]; b2_[co] = cb2[co]; b3_[co] = cb3[co]; }

    float si = 0.f, sj = 0.f;
    {   // epilogue for to
        float y1[4], y2[4], y3[4];
        y1[0] = __uint_as_float((unsigned)A0); y1[1] = __uint_as_float((unsigned)(A0 >> 32));
        y1[2] = __uint_as_float((unsigned)A1); y1[3] = __uint_as_float((unsigned)(A1 >> 32));
        y2[0] = __uint_as_float((unsigned)A2); y2[1] = __uint_as_float((unsigned)(A2 >> 32));
        y2[2] = __uint_as_float((unsigned)A3); y2[3] = __uint_as_float((unsigned)(A3 >> 32));
        y3[0] = __uint_as_float((unsigned)A4); y3[1] = __uint_as_float((unsigned)(A4 >> 32));
        y3[2] = __uint_as_float((unsigned)A5); y3[3] = __uint_as_float((unsigned)(A5 >> 32));
        #pragma unroll
        for (int co = 0; co < 4; co++) {
            float v2 = y2[co] + b2_[co];
            float sg = 1.0f / (1.0f + __expf(-v2));
            float tv = (y1[co] + b1_[co]) + sg + (y3[co] + b3_[co]);
            tv = fmaxf(tv, 0.0f);
            si = fmaf(tv, sFC[to * 4 + co], si);
            sj = fmaf(tv, sFC[248 + to * 4 + co], sj);
        }
    }
    if (to2 < 62) {   // epilogue for to2 (lanes 0..29)
        float y1[4], y2[4], y3[4];
        y1[0] = __uint_as_float((unsigned)B0); y1[1] = __uint_as_float((unsigned)(B0 >> 32));
        y1[2] = __uint_as_float((unsigned)B1); y1[3] = __uint_as_float((unsigned)(B1 >> 32));
        y2[0] = __uint_as_float((unsigned)B2); y2[1] = __uint_as_float((unsigned)(B2 >> 32));
        y2[2] = __uint_as_float((unsigned)B3); y2[3] = __uint_as_float((unsigned)(B3 >> 32));
        y3[0] = __uint_as_float((unsigned)B4); y3[1] = __uint_as_float((unsigned)(B4 >> 32));
        y3[2] = __uint_as_float((unsigned)B5); y3[3] = __uint_as_float((unsigned)(B5 >> 32));
        #pragma unroll
        for (int co = 0; co < 4; co++) {
            float v2 = y2[co] + b2_[co];
            float sg = 1.0f / (1.0f + __expf(-v2));
            float tv = (y1[co] + b1_[co]) + sg + (y3[co] + b3_[co]);
            tv = fmaxf(tv, 0.0f);
            si = fmaf(tv, sFC[to2 * 4 + co], si);
            sj = fmaf(tv, sFC[248 + to2 * 4 + co], sj);
        }
    }
    #pragma unroll
    for (int off = 16; off > 0; off >>= 1) {
        si += __shfl_xor_sync(0xffffffffu, si, off);
        sj += __shfl_xor_sync(0xffffffffu, sj, off);
    }
    if (lane == 0) {
        float fcb = fcbp[0];
        float sif = si + fcb;
        g_eip[bn] = __expf(sif);
        g_ein[bn] = __expf(0.01f * sif);
        g_ejp[bn] = __expf(sj);
        g_ejn[bn] = __expf(0.01f * sj);
    }
}

// ---------------------------------------------------------------------------
// k2: masked softmax. One block handles a 2-batch x 4-row tile of output.
// P/Q column vectors loaded ONCE per block into registers and reused by all
// 8 output rows; A row registers reused across the 2 batches.
// exp(leaky(si+sj+c)) = max(Eip*Ejp[j], Ein*Ejn[j]); masked -> exp(0)=1.
// ---------------------------------------------------------------------------
__global__ void __launch_bounds__(256) softmax_kernel(
    const float* __restrict__ A, float* __restrict__ out)
{
    int tile = blockIdx.x;          // 2048 tiles
    int it   = tile & 511;          // i-tile (4 rows)
    int bp   = tile >> 9;           // batch pair (4)
    int i0   = it * 4;
    int b0   = bp * 2;
    int t    = threadIdx.x;
    int j0   = t * 4;               // columns [j0, j0+4) and [j0+1024, ...)

    // P/Q for both batches, both column chunks (32 regs)
    float4 P00 = *(const float4*)(g_ejp + (b0    ) * NN + j0);
    float4 P01 = *(const float4*)(g_ejp + (b0    ) * NN + j0 + 1024);
    float4 Q00 = *(const float4*)(g_ejn + (b0    ) * NN + j0);
    float4 Q01 = *(const float4*)(g_ejn + (b0    ) * NN + j0 + 1024);
    float4 P10 = *(const float4*)(g_ejp + (b0 + 1) * NN + j0);
    float4 P11 = *(const float4*)(g_ejp + (b0 + 1) * NN + j0 + 1024);
    float4 Q10 = *(const float4*)(g_ejn + (b0 + 1) * NN + j0);
    float4 Q11 = *(const float4*)(g_ejn + (b0 + 1) * NN + j0 + 1024);

    __shared__ float red[2][8];
    __shared__ float s_r[2];

    #pragma unroll 1
    for (int ii = 0; ii < 4; ii++) {
        int i = i0 + ii;
        float4 a0 = __ldg((const float4*)(A + (size_t)i * NN + j0));
        float4 a1 = __ldg((const float4*)(A + (size_t)i * NN + j0 + 1024));

        float acc[2];
        float4 e0[2], e1[2];
        #pragma unroll
        for (int b = 0; b < 2; b++) {
            int row = (b0 + b) * NN + i;
            float Eip = __ldg(g_eip + row);
            float Ein = __ldg(g_ein + row);
            const float4 Pc0 = b ? P10 : P00, Pc1 = b ? P11 : P01;
            const float4 Qc0 = b ? Q10 : Q00, Qc1 = b ? Q11 : Q01;
            e0[b].x = fmaxf(Eip * Pc0.x, Ein * Qc0.x);
            e0[b].y = fmaxf(Eip * Pc0.y, Ein * Qc0.y);
            e0[b].z = fmaxf(Eip * Pc0.z, Ein * Qc0.z);
            e0[b].w = fmaxf(Eip * Pc0.w, Ein * Qc0.w);
            e1[b].x = fmaxf(Eip * Pc1.x, Ein * Qc1.x);
            e1[b].y = fmaxf(Eip * Pc1.y, Ein * Qc1.y);
            e1[b].z = fmaxf(Eip * Pc1.z, Ein * Qc1.z);
            e1[b].w = fmaxf(Eip * Pc1.w, Ein * Qc1.w);
            acc[b] = ((a0.x != 0.f) ? e0[b].x : 1.f) + ((a0.y != 0.f) ? e0[b].y : 1.f)
                   + ((a0.z != 0.f) ? e0[b].z : 1.f) + ((a0.w != 0.f) ? e0[b].w : 1.f)
                   + ((a1.x != 0.f) ? e1[b].x : 1.f) + ((a1.y != 0.f) ? e1[b].y : 1.f)
                   + ((a1.z != 0.f) ? e1[b].z : 1.f) + ((a1.w != 0.f) ? e1[b].w : 1.f);
        }
        #pragma unroll
        for (int off = 16; off > 0; off >>= 1) {
            acc[0] += __shfl_xor_sync(0xffffffffu, acc[0], off);
            acc[1] += __shfl_xor_sync(0xffffffffu, acc[1], off);
        }
        if ((t & 31) == 0) { red[0][t >> 5] = acc[0]; red[1][t >> 5] = acc[1]; }
        __syncthreads();
        if (t < 2) {
            float s = red[t][0] + red[t][1] + red[t][2] + red[t][3]
                    + red[t][4] + red[t][5] + red[t][6] + red[t][7];
            s_r[t] = 1.0f / s;
        }
        __syncthreads();

        #pragma unroll
        for (int b = 0; b < 2; b++) {
            float r = s_r[b];
            float* O = out + ((size_t)((b0 + b) * NN + i)) * NN;
            float4 o0, o1;
            o0.x = e0[b].x * a0.x * r;  o0.y = e0[b].y * a0.y * r;
            o0.z = e0[b].z * a0.z * r;  o0.w = e0[b].w * a0.w * r;
            o1.x = e1[b].x * a1.x * r;  o1.y = e1[b].y * a1.y * r;
            o1.z = e1[b].z * a1.z * r;  o1.w = e1[b].w * a1.w * r;
            __stcs((float4*)(O + j0), o0);
            __stcs((float4*)(O + j0 + 1024), o1);
        }
        __syncthreads();   // protect s_r/red reuse next iteration
    }
}

// ---------------------------------------------------------------------------
extern "C" void kernel_launch(void* const* d_in, const int* in_sizes, int n_in,
                              void* d_out, int out_size) {
    const float* X   = (const float*)d_in[0];
    const float* A   = (const float*)d_in[1];
    const float* cw1 = (const float*)d_in[2];
    const float* cb1 = (const float*)d_in[3];
    const float* cw2 = (const float*)d_in[4];
    const float* cb2 = (const float*)d_in[5];
    const float* cw3 = (const float*)d_in[6];
    const float* cb3 = (const float*)d_in[7];
    const float* fcw = (const float*)d_in[8];
    const float* fcb = (const float*)d_in[9];
    float* out = (float*)d_out;

    score_kernel<<<BN_TOTAL / 8, 256>>>(X, cw1, cw2, cw3, cb1, cb2, cb3, fcw, fcb);
    softmax_kernel<<<2048, 256>>>(A, out);
}

// round 3
// speedup vs baseline: 6.1787x; 1.0809x over previous
#include <cuda_runtime.h>

typedef unsigned long long ull;

#define BN_TOTAL 16384   // B*N
#define NN 2048

__device__ __align__(16) float g_eip[BN_TOTAL];
__device__ __align__(16) float g_ein[BN_TOTAL];
__device__ __align__(16) float g_ejp[BN_TOTAL];
__device__ __align__(16) float g_ejn[BN_TOTAL];

__device__ __forceinline__ void fma2(ull& acc, ull x, ull w) {
    asm("fma.rn.f32x2 %0, %1, %2, %0;" : "+l"(acc) : "l"(x), "l"(w));
}
__device__ __forceinline__ ull pack2(float v) {
    ull r; unsigned u = __float_as_uint(v);
    asm("mov.b64 %0, {%1, %1};" : "=l"(r) : "r"(u));
    return r;
}

// ---------------------------------------------------------------------------
// k1: fused TimeBlock + dot with wi/wj -> exp factors per (b,n).
// Algebraic fold: relu(conv1+b1 + sigmoid(conv2+b2) + conv3+b3)
//               = relu(conv(w1+w3) + (b1+b3) + sigmoid(conv2+b2))
// so only TWO conv stacks (8 outputs) are accumulated, not three.
// One warp per (b,n); lane covers to=lane and to2=lane+32.
// ---------------------------------------------------------------------------
__global__ void __launch_bounds__(256) score_kernel(
    const float* __restrict__ X,
    const float* __restrict__ cw1, const float* __restrict__ cw2,
    const float* __restrict__ cw3,
    const float* __restrict__ cb1, const float* __restrict__ cb2,
    const float* __restrict__ cb3,
    const float* __restrict__ fcw, const float* __restrict__ fcbp)
{
    __shared__ __align__(16) float sX[8 * 1088];   // 8 warps x 64 rows x 17 (pad)
    __shared__ __align__(16) float sW[384];        // [2][k*16+ci][co]: wS then w2
    __shared__ float sFC[496];

    int tid = threadIdx.x;
    // pack conv weights: (co,ci,1,3) -> [c][(k*16+ci)][co], c0 = w1+w3, c1 = w2
    for (int i = tid; i < 384; i += 256) {
        int c   = i / 192;
        int r   = i % 192;
        int pos = r >> 2, co = r & 3;
        int k   = pos >> 4, ci = pos & 15;
        int src = co * 48 + ci * 3 + k;
        sW[i] = (c == 0) ? (cw1[src] + cw3[src]) : cw2[src];
    }
    for (int i = tid; i < 496; i += 256) sFC[i] = fcw[i];

    int warp = tid >> 5, lane = tid & 31;
    int bn = blockIdx.x * 8 + warp;

    // cooperative load of X[bn] (64x16 floats) into padded shared tile
    const float4* Xg = (const float4*)(X + (size_t)bn * 1024);
    #pragma unroll
    for (int q = 0; q < 8; q++) {
        int f = lane + q * 32;
        float4 v = Xg[f];
        int row = f >> 2, c4 = (f & 3) * 4;
        float* d = sX + warp * 1088 + row * 17 + c4;
        d[0] = v.x; d[1] = v.y; d[2] = v.z; d[3] = v.w;
    }
    __syncthreads();

    int to  = lane;        // 0..31
    int to2 = lane + 32;   // 32..63 (valid if < 62)

    ull A0 = 0, A1 = 0, A2 = 0, A3 = 0;    // to : wS pair0/1, w2 pair0/1
    ull B0 = 0, B1 = 0, B2 = 0, B3 = 0;    // to2
    const float* x1 = sX + warp * 1088 + to * 17;
    const float* x2 = x1 + 32 * 17;

    #pragma unroll
    for (int k = 0; k < 3; k++) {
        #pragma unroll
        for (int ci = 0; ci < 16; ci++) {
            int wb = (k * 16 + ci) * 4;
            ull w0 = *(const ull*)(sW + wb);
            ull w1 = *(const ull*)(sW + wb + 2);
            ull w2 = *(const ull*)(sW + 192 + wb);
            ull w3 = *(const ull*)(sW + 192 + wb + 2);
            ull xa = pack2(x1[k * 17 + ci]);
            ull xb = pack2(x2[k * 17 + ci]);
            fma2(A0, xa, w0); fma2(A1, xa, w1);
            fma2(A2, xa, w2); fma2(A3, xa, w3);
            fma2(B0, xb, w0); fma2(B1, xb, w1);
            fma2(B2, xb, w2); fma2(B3, xb, w3);
        }
    }

    float bS[4], b2_[4];
    #pragma unroll
    for (int co = 0; co < 4; co++) { bS[co] = cb1[co] + cb3[co]; b2_[co] = cb2[co]; }

    float si = 0.f, sj = 0.f;
    {   // epilogue for to
        float yS[4], y2[4];
        yS[0] = __uint_as_float((unsigned)A0); yS[1] = __uint_as_float((unsigned)(A0 >> 32));
        yS[2] = __uint_as_float((unsigned)A1); yS[3] = __uint_as_float((unsigned)(A1 >> 32));
        y2[0] = __uint_as_float((unsigned)A2); y2[1] = __uint_as_float((unsigned)(A2 >> 32));
        y2[2] = __uint_as_float((unsigned)A3); y2[3] = __uint_as_float((unsigned)(A3 >> 32));
        #pragma unroll
        for (int co = 0; co < 4; co++) {
            float sg = 1.0f / (1.0f + __expf(-(y2[co] + b2_[co])));
            float tv = fmaxf(yS[co] + bS[co] + sg, 0.0f);
            si = fmaf(tv, sFC[to * 4 + co], si);
            sj = fmaf(tv, sFC[248 + to * 4 + co], sj);
        }
    }
    if (to2 < 62) {   // epilogue for to2 (lanes 0..29)
        float yS[4], y2[4];
        yS[0] = __uint_as_float((unsigned)B0); yS[1] = __uint_as_float((unsigned)(B0 >> 32));
        yS[2] = __uint_as_float((unsigned)B1); yS[3] = __uint_as_float((unsigned)(B1 >> 32));
        y2[0] = __uint_as_float((unsigned)B2); y2[1] = __uint_as_float((unsigned)(B2 >> 32));
        y2[2] = __uint_as_float((unsigned)B3); y2[3] = __uint_as_float((unsigned)(B3 >> 32));
        #pragma unroll
        for (int co = 0; co < 4; co++) {
            float sg = 1.0f / (1.0f + __expf(-(y2[co] + b2_[co])));
            float tv = fmaxf(yS[co] + bS[co] + sg, 0.0f);
            si = fmaf(tv, sFC[to2 * 4 + co], si);
            sj = fmaf(tv, sFC[248 + to2 * 4 + co], sj);
        }
    }
    #pragma unroll
    for (int off = 16; off > 0; off >>= 1) {
        si += __shfl_xor_sync(0xffffffffu, si, off);
        sj += __shfl_xor_sync(0xffffffffu, sj, off);
    }
    if (lane == 0) {
        float fcb = fcbp[0];
        float sif = si + fcb;
        g_eip[bn] = __expf(sif);
        g_ein[bn] = __expf(0.01f * sif);
        g_ejp[bn] = __expf(sj);
        g_ejn[bn] = __expf(0.01f * sj);
    }
}

// ---------------------------------------------------------------------------
// k2: masked softmax. One block = 4 rows of ONE batch (4096 blocks).
// P/Q column vectors in registers (16 regs), shared by the 4 rows.
// All 4 row-sums reduced in a single phase (2 block syncs total);
// e recomputed from register P/Q at write time.
// ---------------------------------------------------------------------------
__global__ void __launch_bounds__(256) softmax_kernel(
    const float* __restrict__ A, float* __restrict__ out)
{
    int tile = blockIdx.x;          // 4096 = 8 batches x 512 row-tiles
    int it   = tile & 511;
    int b    = tile >> 9;
    int i0   = it * 4;
    int t    = threadIdx.x;
    int j0   = t * 4;

    float4 P0 = *(const float4*)(g_ejp + b * NN + j0);
    float4 P1 = *(const float4*)(g_ejp + b * NN + j0 + 1024);
    float4 Q0 = *(const float4*)(g_ejn + b * NN + j0);
    float4 Q1 = *(const float4*)(g_ejn + b * NN + j0 + 1024);

    float4 a0[4], a1[4];
    float Eip[4], Ein[4], acc[4];

    #pragma unroll
    for (int ii = 0; ii < 4; ii++) {
        int i = i0 + ii;
        a0[ii] = __ldg((const float4*)(A + (size_t)i * NN + j0));
        a1[ii] = __ldg((const float4*)(A + (size_t)i * NN + j0 + 1024));
        Eip[ii] = __ldg(g_eip + b * NN + i);
        Ein[ii] = __ldg(g_ein + b * NN + i);
        float e;
        float s = 0.f;
        e = fmaxf(Eip[ii] * P0.x, Ein[ii] * Q0.x); s += (a0[ii].x != 0.f) ? e : 1.f;
        e = fmaxf(Eip[ii] * P0.y, Ein[ii] * Q0.y); s += (a0[ii].y != 0.f) ? e : 1.f;
        e = fmaxf(Eip[ii] * P0.z, Ein[ii] * Q0.z); s += (a0[ii].z != 0.f) ? e : 1.f;
        e = fmaxf(Eip[ii] * P0.w, Ein[ii] * Q0.w); s += (a0[ii].w != 0.f) ? e : 1.f;
        e = fmaxf(Eip[ii] * P1.x, Ein[ii] * Q1.x); s += (a1[ii].x != 0.f) ? e : 1.f;
        e = fmaxf(Eip[ii] * P1.y, Ein[ii] * Q1.y); s += (a1[ii].y != 0.f) ? e : 1.f;
        e = fmaxf(Eip[ii] * P1.z, Ein[ii] * Q1.z); s += (a1[ii].z != 0.f) ? e : 1.f;
        e = fmaxf(Eip[ii] * P1.w, Ein[ii] * Q1.w); s += (a1[ii].w != 0.f) ? e : 1.f;
        acc[ii] = s;
    }

    #pragma unroll
    for (int off = 16; off > 0; off >>= 1) {
        acc[0] += __shfl_xor_sync(0xffffffffu, acc[0], off);
        acc[1] += __shfl_xor_sync(0xffffffffu, acc[1], off);
        acc[2] += __shfl_xor_sync(0xffffffffu, acc[2], off);
        acc[3] += __shfl_xor_sync(0xffffffffu, acc[3], off);
    }

    __shared__ float red[4][8];
    __shared__ float s_r[4];
    if ((t & 31) == 0) {
        int w = t >> 5;
        red[0][w] = acc[0]; red[1][w] = acc[1];
        red[2][w] = acc[2]; red[3][w] = acc[3];
    }
    __syncthreads();
    if (t < 4) {
        float s = red[t][0] + red[t][1] + red[t][2] + red[t][3]
                + red[t][4] + red[t][5] + red[t][6] + red[t][7];
        s_r[t] = 1.0f / s;
    }
    __syncthreads();

    #pragma unroll
    for (int ii = 0; ii < 4; ii++) {
        int i = i0 + ii;
        float r = s_r[ii];
        float Ep = Eip[ii], En = Ein[ii];
        float* O = out + ((size_t)(b * NN + i)) * NN;
        float4 o0, o1;
        o0.x = fmaxf(Ep * P0.x, En * Q0.x) * a0[ii].x * r;
        o0.y = fmaxf(Ep * P0.y, En * Q0.y) * a0[ii].y * r;
        o0.z = fmaxf(Ep * P0.z, En * Q0.z) * a0[ii].z * r;
        o0.w = fmaxf(Ep * P0.w, En * Q0.w) * a0[ii].w * r;
        o1.x = fmaxf(Ep * P1.x, En * Q1.x) * a1[ii].x * r;
        o1.y = fmaxf(Ep * P1.y, En * Q1.y) * a1[ii].y * r;
        o1.z = fmaxf(Ep * P1.z, En * Q1.z) * a1[ii].z * r;
        o1.w = fmaxf(Ep * P1.w, En * Q1.w) * a1[ii].w * r;
        __stcs((float4*)(O + j0), o0);
        __stcs((float4*)(O + j0 + 1024), o1);
    }
}

// ---------------------------------------------------------------------------
extern "C" void kernel_launch(void* const* d_in, const int* in_sizes, int n_in,
                              void* d_out, int out_size) {
    const float* X   = (const float*)d_in[0];
    const float* A   = (const float*)d_in[1];
    const float* cw1 = (const float*)d_in[2];
    const float* cb1 = (const float*)d_in[3];
    const float* cw2 = (const float*)d_in[4];
    const float* cb2 = (const float*)d_in[5];
    const float* cw3 = (const float*)d_in[6];
    const float* cb3 = (const float*)d_in[7];
    const float* fcw = (const float*)d_in[8];
    const float* fcb = (const float*)d_in[9];
    float* out = (float*)d_out;

    score_kernel<<<BN_TOTAL / 8, 256>>>(X, cw1, cw2, cw3, cb1, cb2, cb3, fcw, fcb);
    softmax_kernel<<<4096, 256>>>(A, out);
}

// round 4
// speedup vs baseline: 6.3672x; 1.0305x over previous
#include <cuda_runtime.h>
#include <cstdint>

typedef unsigned long long ull;

#define BN_TOTAL 16384   // B*N
#define NN 2048

__device__ __align__(16) float g_eip[BN_TOTAL];
__device__ __align__(16) float g_ein[BN_TOTAL];
__device__ __align__(16) float g_ejp[BN_TOTAL];
__device__ __align__(16) float g_ejn[BN_TOTAL];

__device__ __forceinline__ void fma2(ull& acc, ull x, ull w) {
    asm("fma.rn.f32x2 %0, %1, %2, %0;" : "+l"(acc) : "l"(x), "l"(w));
}
__device__ __forceinline__ ull pack2(float v) {
    ull r; unsigned u = __float_as_uint(v);
    asm("mov.b64 %0, {%1, %1};" : "=l"(r) : "r"(u));
    return r;
}
__device__ __forceinline__ void cp16(uint32_t dst, const void* src) {
    asm volatile("cp.async.cg.shared.global [%0], [%1], 16;" :: "r"(dst), "l"(src));
}

#define XSTRIDE 20   // floats per row: 16B-aligned chunks, 4-way-max bank conflicts

// ---------------------------------------------------------------------------
// k1: fused TimeBlock + dot with wi/wj -> exp factors per (b,n).
// relu(conv1+b1+sigmoid(conv2+b2)+conv3+b3) = relu(conv(w1+w3)+(b1+b3)+sig(..))
// One warp per (b,n), fully decoupled: cp.async tile load + __syncwarp only.
// Lane covers to=lane and to2=lane+32.
// ---------------------------------------------------------------------------
__global__ void __launch_bounds__(256) score_kernel(
    const float* __restrict__ X,
    const float* __restrict__ cw1, const float* __restrict__ cw2,
    const float* __restrict__ cw3,
    const float* __restrict__ cb1, const float* __restrict__ cb2,
    const float* __restrict__ cb3,
    const float* __restrict__ fcw, const float* __restrict__ fcbp)
{
    __shared__ __align__(16) float sX[8 * 64 * XSTRIDE];  // 40 KB
    __shared__ __align__(16) float sW[384];               // [2][k*16+ci][co]
    __shared__ float sFC[496];

    int tid = threadIdx.x;
    for (int i = tid; i < 384; i += 256) {
        int c   = i / 192;
        int r   = i % 192;
        int pos = r >> 2, co = r & 3;
        int k   = pos >> 4, ci = pos & 15;
        int src = co * 48 + ci * 3 + k;
        sW[i] = (c == 0) ? (cw1[src] + cw3[src]) : cw2[src];
    }
    for (int i = tid; i < 496; i += 256) sFC[i] = fcw[i];
    __syncthreads();   // weights ready; warps independent from here on

    int warp = tid >> 5, lane = tid & 31;
    int bn = blockIdx.x * 8 + warp;

    float* wbuf = sX + warp * (64 * XSTRIDE);
    uint32_t wbuf_s = (uint32_t)__cvta_generic_to_shared(wbuf);
    const float* Xg = X + (size_t)bn * 1024;

    // async load: 8 chunks of 16B per lane -> 64 rows x 16 cols (stride 20)
    #pragma unroll
    for (int q = 0; q < 8; q++) {
        int f = q * 32 + lane;
        int row = f >> 2, c4 = (f & 3) * 4;
        cp16(wbuf_s + (row * XSTRIDE + c4) * 4, Xg + f * 4);
    }
    asm volatile("cp.async.commit_group;");
    asm volatile("cp.async.wait_group 0;");
    __syncwarp();

    int to  = lane;
    int to2 = lane + 32;

    ull A0 = 0, A1 = 0, A2 = 0, A3 = 0;
    ull B0 = 0, B1 = 0, B2 = 0, B3 = 0;
    const float* x1 = wbuf + to * XSTRIDE;
    const float* x2 = x1 + 32 * XSTRIDE;

    #pragma unroll
    for (int k = 0; k < 3; k++) {
        #pragma unroll
        for (int ci = 0; ci < 16; ci++) {
            int wb = (k * 16 + ci) * 4;
            ull w0 = *(const ull*)(sW + wb);
            ull w1 = *(const ull*)(sW + wb + 2);
            ull w2 = *(const ull*)(sW + 192 + wb);
            ull w3 = *(const ull*)(sW + 192 + wb + 2);
            ull xa = pack2(x1[k * XSTRIDE + ci]);
            ull xb = pack2(x2[k * XSTRIDE + ci]);
            fma2(A0, xa, w0); fma2(A1, xa, w1);
            fma2(A2, xa, w2); fma2(A3, xa, w3);
            fma2(B0, xb, w0); fma2(B1, xb, w1);
            fma2(B2, xb, w2); fma2(B3, xb, w3);
        }
    }

    float bS[4], b2_[4];
    #pragma unroll
    for (int co = 0; co < 4; co++) { bS[co] = cb1[co] + cb3[co]; b2_[co] = cb2[co]; }

    float si = 0.f, sj = 0.f;
    {
        float yS[4], y2[4];
        yS[0] = __uint_as_float((unsigned)A0); yS[1] = __uint_as_float((unsigned)(A0 >> 32));
        yS[2] = __uint_as_float((unsigned)A1); yS[3] = __uint_as_float((unsigned)(A1 >> 32));
        y2[0] = __uint_as_float((unsigned)A2); y2[1] = __uint_as_float((unsigned)(A2 >> 32));
        y2[2] = __uint_as_float((unsigned)A3); y2[3] = __uint_as_float((unsigned)(A3 >> 32));
        #pragma unroll
        for (int co = 0; co < 4; co++) {
            float sg = 1.0f / (1.0f + __expf(-(y2[co] + b2_[co])));
            float tv = fmaxf(yS[co] + bS[co] + sg, 0.0f);
            si = fmaf(tv, sFC[to * 4 + co], si);
            sj = fmaf(tv, sFC[248 + to * 4 + co], sj);
        }
    }
    if (to2 < 62) {
        float yS[4], y2[4];
        yS[0] = __uint_as_float((unsigned)B0); yS[1] = __uint_as_float((unsigned)(B0 >> 32));
        yS[2] = __uint_as_float((unsigned)B1); yS[3] = __uint_as_float((unsigned)(B1 >> 32));
        y2[0] = __uint_as_float((unsigned)B2); y2[1] = __uint_as_float((unsigned)(B2 >> 32));
        y2[2] = __uint_as_float((unsigned)B3); y2[3] = __uint_as_float((unsigned)(B3 >> 32));
        #pragma unroll
        for (int co = 0; co < 4; co++) {
            float sg = 1.0f / (1.0f + __expf(-(y2[co] + b2_[co])));
            float tv = fmaxf(yS[co] + bS[co] + sg, 0.0f);
            si = fmaf(tv, sFC[to2 * 4 + co], si);
            sj = fmaf(tv, sFC[248 + to2 * 4 + co], sj);
        }
    }
    #pragma unroll
    for (int off = 16; off > 0; off >>= 1) {
        si += __shfl_xor_sync(0xffffffffu, si, off);
        sj += __shfl_xor_sync(0xffffffffu, sj, off);
    }
    if (lane == 0) {
        float fcb = fcbp[0];
        float sif = si + fcb;
        g_eip[bn] = __expf(sif);
        g_ein[bn] = __expf(0.01f * sif);
        g_ejp[bn] = __expf(sj);
        g_ejn[bn] = __expf(0.01f * sj);
    }
}

// ---------------------------------------------------------------------------
// k2: masked softmax. One block = 4 rows of ONE batch (4096 blocks).
// A entries are exactly {0,1}: only a 1-bit mask per element is kept
// (packed, 8 bits/row -> one u32 for all 4 rows). P/Q in registers,
// e recomputed at write time. ~45 regs -> 5-6 CTAs/SM.
// ---------------------------------------------------------------------------
__global__ void __launch_bounds__(256) softmax_kernel(
    const float* __restrict__ A, float* __restrict__ out)
{
    int tile = blockIdx.x;          // 4096 = 8 batches x 512 row-tiles
    int it   = tile & 511;
    int b    = tile >> 9;
    int i0   = it * 4;
    int t    = threadIdx.x;
    int j0   = t * 4;

    float4 P0 = *(const float4*)(g_ejp + b * NN + j0);
    float4 P1 = *(const float4*)(g_ejp + b * NN + j0 + 1024);
    float4 Q0 = *(const float4*)(g_ejn + b * NN + j0);
    float4 Q1 = *(const float4*)(g_ejn + b * NN + j0 + 1024);

    float Eip[4], Ein[4], acc[4];
    unsigned mask = 0;              // bit (ii*8 + pos)

    #pragma unroll
    for (int ii = 0; ii < 4; ii++) {
        int i = i0 + ii;
        float4 a0 = __ldg((const float4*)(A + (size_t)i * NN + j0));
        float4 a1 = __ldg((const float4*)(A + (size_t)i * NN + j0 + 1024));
        unsigned m = (a0.x != 0.f)       | ((a0.y != 0.f) << 1)
                   | ((a0.z != 0.f) << 2) | ((a0.w != 0.f) << 3)
                   | ((a1.x != 0.f) << 4) | ((a1.y != 0.f) << 5)
                   | ((a1.z != 0.f) << 6) | ((a1.w != 0.f) << 7);
        mask |= m << (ii * 8);
        float Ep = __ldg(g_eip + b * NN + i);
        float En = __ldg(g_ein + b * NN + i);
        Eip[ii] = Ep; Ein[ii] = En;
        float s = 0.f, e;
        e = fmaxf(Ep * P0.x, En * Q0.x); s += (m & 1u)   ? e : 1.f;
        e = fmaxf(Ep * P0.y, En * Q0.y); s += (m & 2u)   ? e : 1.f;
        e = fmaxf(Ep * P0.z, En * Q0.z); s += (m & 4u)   ? e : 1.f;
        e = fmaxf(Ep * P0.w, En * Q0.w); s += (m & 8u)   ? e : 1.f;
        e = fmaxf(Ep * P1.x, En * Q1.x); s += (m & 16u)  ? e : 1.f;
        e = fmaxf(Ep * P1.y, En * Q1.y); s += (m & 32u)  ? e : 1.f;
        e = fmaxf(Ep * P1.z, En * Q1.z); s += (m & 64u)  ? e : 1.f;
        e = fmaxf(Ep * P1.w, En * Q1.w); s += (m & 128u) ? e : 1.f;
        acc[ii] = s;
    }

    #pragma unroll
    for (int off = 16; off > 0; off >>= 1) {
        acc[0] += __shfl_xor_sync(0xffffffffu, acc[0], off);
        acc[1] += __shfl_xor_sync(0xffffffffu, acc[1], off);
        acc[2] += __shfl_xor_sync(0xffffffffu, acc[2], off);
        acc[3] += __shfl_xor_sync(0xffffffffu, acc[3], off);
    }

    __shared__ float red[4][8];
    __shared__ float s_r[4];
    if ((t & 31) == 0) {
        int w = t >> 5;
        red[0][w] = acc[0]; red[1][w] = acc[1];
        red[2][w] = acc[2]; red[3][w] = acc[3];
    }
    __syncthreads();
    if (t < 4) {
        float s = red[t][0] + red[t][1] + red[t][2] + red[t][3]
                + red[t][4] + red[t][5] + red[t][6] + red[t][7];
        s_r[t] = 1.0f / s;
    }
    __syncthreads();

    #pragma unroll
    for (int ii = 0; ii < 4; ii++) {
        int i = i0 + ii;
        float r = s_r[ii];
        float Ep = Eip[ii], En = Ein[ii];
        unsigned m = mask >> (ii * 8);
        float* O = out + ((size_t)(b * NN + i)) * NN;
        float4 o0, o1;
        o0.x = (m & 1u)   ? fmaxf(Ep * P0.x, En * Q0.x) * r : 0.f;
        o0.y = (m & 2u)   ? fmaxf(Ep * P0.y, En * Q0.y) * r : 0.f;
        o0.z = (m & 4u)   ? fmaxf(Ep * P0.z, En * Q0.z) * r : 0.f;
        o0.w = (m & 8u)   ? fmaxf(Ep * P0.w, En * Q0.w) * r : 0.f;
        o1.x = (m & 16u)  ? fmaxf(Ep * P1.x, En * Q1.x) * r : 0.f;
        o1.y = (m & 32u)  ? fmaxf(Ep * P1.y, En * Q1.y) * r : 0.f;
        o1.z = (m & 64u)  ? fmaxf(Ep * P1.z, En * Q1.z) * r : 0.f;
        o1.w = (m & 128u) ? fmaxf(Ep * P1.w, En * Q1.w) * r : 0.f;
        __stcs((float4*)(O + j0), o0);
        __stcs((float4*)(O + j0 + 1024), o1);
    }
}

// ---------------------------------------------------------------------------
extern "C" void kernel_launch(void* const* d_in, const int* in_sizes, int n_in,
                              void* d_out, int out_size) {
    const float* X   = (const float*)d_in[0];
    const float* A   = (const float*)d_in[1];
    const float* cw1 = (const float*)d_in[2];
    const float* cb1 = (const float*)d_in[3];
    const float* cw2 = (const float*)d_in[4];
    const float* cb2 = (const float*)d_in[5];
    const float* cw3 = (const float*)d_in[6];
    const float* cb3 = (const float*)d_in[7];
    const float* fcw = (const float*)d_in[8];
    const float* fcb = (const float*)d_in[9];
    float* out = (float*)d_out;

    score_kernel<<<BN_TOTAL / 8, 256>>>(X, cw1, cw2, cw3, cb1, cb2, cb3, fcw, fcb);
    softmax_kernel<<<4096, 256>>>(A, out);
}